// round 15
// baseline (speedup 1.0000x reference)
#include <cuda_runtime.h>
#include <cuda_fp16.h>

#define B_   64
#define T_   512
#define DIN  256
#define H_   1024
#define DOUT 256
#define NCTA 128
#define NT   256

constexpr int KT0 = 16;
constexpr int KTH = 64;
constexpr size_t FSZ0 = (size_t)64 * 3 * KT0 * 64;
constexpr size_t FSZH = (size_t)64 * 3 * KTH * 64;
constexpr size_t FB0 = 0, FB1 = FSZ0, FB2 = FSZ0 + FSZH, FB3 = FSZ0 + 2 * FSZH;

__device__ uint4 g_wA[FSZ0 + 3 * FSZH];            // fp16 frag table (hi, lo)
__device__ float g_h0f[2][B_ * H_], g_h1f[2][B_ * H_];
__device__ unsigned g_h0x[2][KTH * B_ * 8];        // fp16 act frags [kg][b][qq][sel]
__device__ unsigned g_h1x[2][KTH * B_ * 8];
__device__ unsigned g_xx[(size_t)T_ * KT0 * B_ * 8];
__device__ unsigned g_bar, g_done;

__device__ __forceinline__ unsigned short hfb(float v) {
    __half h = __float2half_rn(v);
    return *reinterpret_cast<unsigned short*>(&h);
}
__device__ __forceinline__ float h2f(unsigned short u) {
    __half h = *reinterpret_cast<__half*>(&u);
    return __half2float(h);
}
__device__ __forceinline__ unsigned pk(float a, float b) {
    return (unsigned)hfb(a) | ((unsigned)hfb(b) << 16);
}
__device__ __forceinline__ float resid(float w) { return w - h2f(hfb(w)); }
__device__ __forceinline__ float sigf(float x) {
    return __fdividef(1.0f, 1.0f + __expf(-x));
}
__device__ __forceinline__ float tanh_(float x) {
    return __fdividef(2.0f, 1.0f + __expf(-2.0f * x)) - 1.0f;
}
__device__ __forceinline__ void mmaf16(float (&d)[4], const uint4 a,
                                       unsigned b0, unsigned b1) {
    asm volatile(
        "mma.sync.aligned.m16n8k16.row.col.f32.f16.f16.f32 "
        "{%0,%1,%2,%3},{%4,%5,%6,%7},{%8,%9},{%0,%1,%2,%3};"
        : "+f"(d[0]), "+f"(d[1]), "+f"(d[2]), "+f"(d[3])
        : "r"(a.x), "r"(a.y), "r"(a.z), "r"(a.w), "r"(b0), "r"(b1));
}
__device__ __forceinline__ void grid_sync(unsigned gen) {
    __syncthreads();
    if (threadIdx.x == 0) {
        __threadfence();
        atomicAdd(&g_bar, 1u);
        while (*((volatile unsigned*)&g_bar) < gen * NCTA) { }
        __threadfence();
    }
    __syncthreads();
}

// Two MMA chains over CNT kg (one n8 tile, full local K range).
template<int CNT>
__device__ __forceinline__ void mloop2(
    const uint4* __restrict__ f1, const uint4* __restrict__ f2,
    const uint2* __restrict__ bp, float (&x1)[4], float (&x2)[4])
{
#pragma unroll 8
    for (int k = 0; k < CNT; ++k) {
        uint4 A = f1[0], Bv = f2[0];
        uint2 v = bp[0];
        mmaf16(x1, A, v.x, v.y);
        mmaf16(x2, Bv, v.x, v.y);
        f1 += 64; f2 += 64; bp += 256;
    }
}

__global__ void __launch_bounds__(NT, 1) gru_ng(
    const float* __restrict__ x,
    const float* __restrict__ Wi0, const float* __restrict__ Wh0,
    const float* __restrict__ bi0, const float* __restrict__ bh0,
    const float* __restrict__ Wi1, const float* __restrict__ Wh1,
    const float* __restrict__ bi1, const float* __restrict__ bh1,
    const float* __restrict__ Wo,  const float* __restrict__ bo,
    float* __restrict__ out)
{
    __shared__ float ex[2][4][16][33];   // [layer][r,z,ni,nh][jl][bl] ~16.9 KB

    const int tid  = threadIdx.x, lane = tid & 31, warp = tid >> 5;
    const int cta  = blockIdx.x;
    const int jt   = cta >> 1;      // j-tile (16 h-units)
    const int bs   = cta & 1;       // batch half (32)
    const int gg   = warp >> 2;     // 0: r/z warps, 1: n hi/lo warps
    const int nq   = warp & 3;      // n8 tile within the batch half

    // ---- prep: x -> single-fp16 fragment words (R14-verified) ----
    {
        const int XW = T_ * KT0 * B_ * 8;
        for (int w = cta * NT + tid; w < XW; w += NCTA * NT) {
            int sel = w & 1, qq = (w >> 1) & 3, b = (w >> 3) & 63;
            int kg = (w >> 9) & 15, t = w >> 13;
            int k0 = kg * 16 + qq * 2 + sel * 8;
            g_xx[w] = pk(x[((size_t)b * T_ + t) * DIN + k0],
                         x[((size_t)b * T_ + t) * DIN + k0 + 1]);
        }
    }
    // ---- zero initial state (buffer 1 read first) ----
    for (int i = cta * NT + tid; i < KTH * B_ * 8; i += NCTA * NT) {
        g_h0x[1][i] = 0u; g_h1x[1][i] = 0u;
    }
    for (int i = cta * NT + tid; i < B_ * H_; i += NCTA * NT) {
        g_h0f[1][i] = 0.f; g_h1f[1][i] = 0.f;
    }
    // ---- weights -> fp16 hi/lo fragment table (R5 layout) ----
    {
        const float* Wp[4] = { Wi0, Wh0, Wi1, Wh1 };
        const int    Kp[4] = { DIN, H_, H_, H_ };
        const size_t Fp[4] = { FB0, FB1, FB2, FB3 };
        for (int p = 0; p < 4; ++p) {
            const int K = Kp[p], KT = K / 16;
            const float* W = Wp[p];
            const int total = 64 * 3 * KT * 32;
            for (int i = cta * NT + tid; i < total; i += NCTA * NT) {
                int l = i & 31, item = i >> 5;
                int kg = item % KT, g = (item / KT) % 3, jtt = item / (KT * 3);
                int m = l >> 2, kb = 2 * (l & 3);
                const float* r0 = W + (size_t)(g * H_ + jtt * 16 + m) * K + kg * 16 + kb;
                const float* r1 = r0 + 8 * (size_t)K;
                float w00 = r0[0], w01 = r0[1], w02 = r0[8], w03 = r0[9];
                float w10 = r1[0], w11 = r1[1], w12 = r1[8], w13 = r1[9];
                uint4 hv, lv;
                hv.x = pk(w00, w01); hv.y = pk(w10, w11);
                hv.z = pk(w02, w03); hv.w = pk(w12, w13);
                lv.x = pk(resid(w00), resid(w01)); lv.y = pk(resid(w10), resid(w11));
                lv.z = pk(resid(w02), resid(w03)); lv.w = pk(resid(w12), resid(w13));
                size_t base = Fp[p] + ((size_t)(jtt * 3 + g) * KT + kg) * 64;
                g_wA[base + l] = hv;
                g_wA[base + 32 + l] = lv;
            }
        }
    }

    // ---- warp fragment pointers: two chains per warp, full K ----
    const uint4* f1_0x; const uint4* f2_0x;   // layer0 x segment
    const uint4* f1_0h; const uint4* f2_0h;   // layer0 h segment
    const uint4* f1_1i; const uint4* f2_1i;   // layer1 input segment
    const uint4* f1_1h; const uint4* f2_1h;   // layer1 hidden segment
    {
        const uint4* base0 = g_wA + FB0 + (size_t)jt * 3 * KT0 * 64 + lane;
        const uint4* base1 = g_wA + FB1 + (size_t)jt * 3 * KTH * 64 + lane;
        const uint4* base2 = g_wA + FB2 + (size_t)jt * 3 * KTH * 64 + lane;
        const uint4* base3 = g_wA + FB3 + (size_t)jt * 3 * KTH * 64 + lane;
        if (gg == 0) {   // R hi, Z hi
            f1_0x = base0;                f2_0x = base0 + KT0 * 64;
            f1_0h = base1;                f2_0h = base1 + KTH * 64;
            f1_1i = base2;                f2_1i = base2 + KTH * 64;
            f1_1h = base3;                f2_1h = base3 + KTH * 64;
        } else {         // N hi, N lo
            f1_0x = base0 + 2 * KT0 * 64; f2_0x = f1_0x + 32;
            f1_0h = base1 + 2 * KTH * 64; f2_0h = f1_0h + 32;
            f1_1i = base2 + 2 * KTH * 64; f2_1i = f1_1i + 32;
            f1_1h = base3 + 2 * KTH * 64; f2_1h = f1_1h + 32;
        }
    }
    const unsigned boff2 = (unsigned)((bs * 32 + nq * 8) * 4
                                      + (lane >> 2) * 4 + (lane & 3));

    // ---- gate-thread biases: thread gates (jl, jl+1) x one b ----
    const int gjl = (tid >> 5) * 2;           // local j pair base
    const int gb  = bs * 32 + (tid & 31);     // global batch row
    const int tb  = tid & 31;
    float bv0[2][4], bv1[2][4];
#pragma unroll
    for (int jj = 0; jj < 2; ++jj) {
        int j = jt * 16 + gjl + jj;
        bv0[jj][0] = bi0[j] + bh0[j];
        bv0[jj][1] = bi0[H_ + j] + bh0[H_ + j];
        bv0[jj][2] = bi0[2 * H_ + j];
        bv0[jj][3] = bh0[2 * H_ + j];
        bv1[jj][0] = bi1[j] + bh1[j];
        bv1[jj][1] = bi1[H_ + j] + bh1[H_ + j];
        bv1[jj][2] = bi1[2 * H_ + j];
        bv1[jj][3] = bh1[2 * H_ + j];
    }

    unsigned gen = 0;
    grid_sync(++gen);   // prep visible

    for (int p = 0; p <= T_; ++p) {
        const int rb0 = (p + 1) & 1;
        // ---- layer0(t=p) GEMMs ----
        if (p < T_) {
            float aA[4] = {}, aB[4] = {}, aC[4] = {}, aD[4] = {};
            const uint2* bxx = (const uint2*)g_xx + (size_t)p * 4096 + boff2;
            const uint2* bxh = (const uint2*)g_h0x[rb0] + boff2;
            if (gg == 0) {
                mloop2<KT0>(f1_0x, f2_0x, bxx, aA, aB);
                mloop2<KTH>(f1_0h, f2_0h, bxh, aA, aB);
            } else {
                mloop2<KT0>(f1_0x, f2_0x, bxx, aA, aB);   // ni hi, lo
                mloop2<KTH>(f1_0h, f2_0h, bxh, aC, aD);   // nh hi, lo
            }
#pragma unroll
            for (int e = 0; e < 4; ++e) {
                int jl = (lane >> 2) + 8 * (e >> 1);
                int bl = nq * 8 + 2 * (lane & 3) + (e & 1);
                if (gg == 0) {
                    ex[0][0][jl][bl] = aA[e];
                    ex[0][1][jl][bl] = aB[e];
                } else {
                    ex[0][2][jl][bl] = aA[e] + aB[e];
                    ex[0][3][jl][bl] = aC[e] + aD[e];
                }
            }
        }
        // ---- layer1(t=p-1) GEMMs ----
        if (p > 0) {
            float aA[4] = {}, aB[4] = {}, aC[4] = {}, aD[4] = {};
            const uint2* bh0v = (const uint2*)g_h0x[rb0] + boff2;
            const uint2* bh1v = (const uint2*)g_h1x[p & 1] + boff2;
            if (gg == 0) {
                mloop2<KTH>(f1_1i, f2_1i, bh0v, aA, aB);
                mloop2<KTH>(f1_1h, f2_1h, bh1v, aA, aB);
            } else {
                mloop2<KTH>(f1_1i, f2_1i, bh0v, aA, aB);  // ni hi, lo
                mloop2<KTH>(f1_1h, f2_1h, bh1v, aC, aD);  // nh hi, lo
            }
#pragma unroll
            for (int e = 0; e < 4; ++e) {
                int jl = (lane >> 2) + 8 * (e >> 1);
                int bl = nq * 8 + 2 * (lane & 3) + (e & 1);
                if (gg == 0) {
                    ex[1][0][jl][bl] = aA[e];
                    ex[1][1][jl][bl] = aB[e];
                } else {
                    ex[1][2][jl][bl] = aA[e] + aB[e];
                    ex[1][3][jl][bl] = aC[e] + aD[e];
                }
            }
        }
        __syncthreads();
        // ---- local gate passes (16 j x 32 b per CTA) ----
        if (p < T_) {
#pragma unroll
            for (int jj = 0; jj < 2; ++jj) {
                int jl = gjl + jj, j = jt * 16 + jl;
                float r  = sigf(ex[0][0][jl][tb] + bv0[jj][0]);
                float z  = sigf(ex[0][1][jl][tb] + bv0[jj][1]);
                float n  = tanh_(ex[0][2][jl][tb] + bv0[jj][2]
                                 + r * (ex[0][3][jl][tb] + bv0[jj][3]));
                float hp = g_h0f[rb0][gb * H_ + j];
                float h  = n + z * (hp - n);
                g_h0f[p & 1][gb * H_ + j] = h;
                int kg = j >> 4, pw = (j & 15) >> 1, qq = pw & 3, sl = pw >> 2;
                unsigned idx = (unsigned)(((kg * 64 + gb) * 4 + qq) * 2 + sl);
                reinterpret_cast<unsigned short*>(g_h0x[p & 1] + idx)[j & 1] = hfb(h);
            }
        }
        if (p > 0) {
#pragma unroll
            for (int jj = 0; jj < 2; ++jj) {
                int jl = gjl + jj, j = jt * 16 + jl;
                float r  = sigf(ex[1][0][jl][tb] + bv1[jj][0]);
                float z  = sigf(ex[1][1][jl][tb] + bv1[jj][1]);
                float n  = tanh_(ex[1][2][jl][tb] + bv1[jj][2]
                                 + r * (ex[1][3][jl][tb] + bv1[jj][3]));
                float hp = g_h1f[p & 1][gb * H_ + j];
                float h  = n + z * (hp - n);
                g_h1f[(p + 1) & 1][gb * H_ + j] = h;
                int kg = j >> 4, pw = (j & 15) >> 1, qq = pw & 3, sl = pw >> 2;
                unsigned idx = (unsigned)(((kg * 64 + gb) * 4 + qq) * 2 + sl);
                reinterpret_cast<unsigned short*>(g_h1x[(p + 1) & 1] + idx)[j & 1] = hfb(h);
            }
        }
        grid_sync(++gen);
    }

    // ---- output projection: h1(511) in g_h1f[1] ----
    if (tid < 128) {
        const int o = cta * 2 + (tid >> 6);
        const int b = tid & 63;
        const float* w  = Wo + (size_t)o * H_;
        const float* hv = g_h1f[1] + (size_t)b * H_;
        float acc = 0.f;
#pragma unroll 4
        for (int k = 0; k < H_; k += 4) {
            float4 wv = *(const float4*)(w + k);
            float4 h4 = *(const float4*)(hv + k);
            acc += wv.x * h4.x + wv.y * h4.y + wv.z * h4.z + wv.w * h4.w;
        }
        out[(size_t)b * DOUT + o] = acc + bo[o];
    }

    // ---- reset persistent counters for next replay ----
    __syncthreads();
    if (tid == 0) {
        unsigned old = atomicAdd(&g_done, 1u);
        if (old == NCTA - 1u) {
            g_bar = 0u;
            g_done = 0u;
            __threadfence();
        }
    }
}

extern "C" void kernel_launch(void* const* d_in, const int* in_sizes, int n_in,
                              void* d_out, int out_size)
{
    gru_ng<<<NCTA, NT>>>(
        (const float*)d_in[0], (const float*)d_in[1], (const float*)d_in[2],
        (const float*)d_in[3], (const float*)d_in[4], (const float*)d_in[5],
        (const float*)d_in[6], (const float*)d_in[7], (const float*)d_in[8],
        (const float*)d_in[9], (const float*)d_in[10], (float*)d_out);
}

// round 16
// speedup vs baseline: 1.3651x; 1.3651x over previous
#include <cuda_runtime.h>
#include <cuda_fp16.h>

#define B_   64
#define T_   512
#define DIN  256
#define H_   1024
#define DOUT 256
#define NCTA 128
#define NT   256

constexpr int KT0 = 16;
constexpr int KTH = 64;
constexpr size_t FSZ0 = (size_t)64 * 3 * KT0 * 64;
constexpr size_t FSZH = (size_t)64 * 3 * KTH * 64;
constexpr size_t FB0 = 0, FB1 = FSZ0, FB2 = FSZ0 + FSZH, FB3 = FSZ0 + 2 * FSZH;

__device__ uint4 g_wA[FSZ0 + 3 * FSZH];            // fp16 frag table (hi, lo)
__device__ float g_h0f[2][B_ * H_], g_h1f[2][B_ * H_];
__device__ unsigned g_h0x[2][KTH * B_ * 8];        // fp16 act frags [kg][b][qq][sel]
__device__ unsigned g_h1x[2][KTH * B_ * 8];
__device__ unsigned g_xx[(size_t)T_ * KT0 * B_ * 8];
__device__ unsigned g_bar, g_done;

__device__ __forceinline__ unsigned short hfb(float v) {
    __half h = __float2half_rn(v);
    return *reinterpret_cast<unsigned short*>(&h);
}
__device__ __forceinline__ float h2f(unsigned short u) {
    __half h = *reinterpret_cast<__half*>(&u);
    return __half2float(h);
}
__device__ __forceinline__ unsigned pk(float a, float b) {
    return (unsigned)hfb(a) | ((unsigned)hfb(b) << 16);
}
__device__ __forceinline__ float resid(float w) { return w - h2f(hfb(w)); }
__device__ __forceinline__ float sigf(float x) {
    return __fdividef(1.0f, 1.0f + __expf(-x));
}
__device__ __forceinline__ float tanh_(float x) {
    return __fdividef(2.0f, 1.0f + __expf(-2.0f * x)) - 1.0f;
}
__device__ __forceinline__ void mmaf16(float (&d)[4], const uint4 a,
                                       unsigned b0, unsigned b1) {
    asm volatile(
        "mma.sync.aligned.m16n8k16.row.col.f32.f16.f16.f32 "
        "{%0,%1,%2,%3},{%4,%5,%6,%7},{%8,%9},{%0,%1,%2,%3};"
        : "+f"(d[0]), "+f"(d[1]), "+f"(d[2]), "+f"(d[3])
        : "r"(a.x), "r"(a.y), "r"(a.z), "r"(a.w), "r"(b0), "r"(b1));
}
__device__ __forceinline__ void grid_sync(unsigned gen) {
    __syncthreads();
    if (threadIdx.x == 0) {
        __threadfence();
        atomicAdd(&g_bar, 1u);
        while (*((volatile unsigned*)&g_bar) < gen * NCTA) { }
        __threadfence();
    }
    __syncthreads();
}

// 8 independent MMAs per kg: 4 A-chains (R,Z,Nhi,Nlo) x 2 n8-tiles.
template<int CNT>
__device__ __forceinline__ void mloop4(
    const uint4* __restrict__ fR, const uint4* __restrict__ fZ,
    const uint4* __restrict__ fNh, const uint4* __restrict__ fNl,
    const uint2* __restrict__ bp,
    float (&aR)[2][4], float (&aZ)[2][4],
    float (&aNm)[2][4], float (&aNx)[2][4])
{
#pragma unroll 4
    for (int k = 0; k < CNT; ++k) {
        uint4 A0 = fR[0], A1 = fZ[0], A2 = fNh[0], A3 = fNl[0];
        uint2 v0 = bp[0], v1 = bp[32];
        mmaf16(aR[0], A0, v0.x, v0.y);  mmaf16(aR[1], A0, v1.x, v1.y);
        mmaf16(aZ[0], A1, v0.x, v0.y);  mmaf16(aZ[1], A1, v1.x, v1.y);
        mmaf16(aNm[0], A2, v0.x, v0.y); mmaf16(aNm[1], A2, v1.x, v1.y);
        mmaf16(aNx[0], A3, v0.x, v0.y); mmaf16(aNx[1], A3, v1.x, v1.y);
        fR += 64; fZ += 64; fNh += 64; fNl += 64; bp += 256;
    }
}

__global__ void __launch_bounds__(NT, 1) gru_loc(
    const float* __restrict__ x,
    const float* __restrict__ Wi0, const float* __restrict__ Wh0,
    const float* __restrict__ bi0, const float* __restrict__ bh0,
    const float* __restrict__ Wi1, const float* __restrict__ Wh1,
    const float* __restrict__ bi1, const float* __restrict__ bh1,
    const float* __restrict__ Wo,  const float* __restrict__ bo,
    float* __restrict__ out)
{
    __shared__ float part[4][4][16][33];   // [ksub][q: r,z,ni,nh][jl][bl] 33.8 KB

    const int tid  = threadIdx.x, lane = tid & 31, warp = tid >> 5;
    const int cta  = blockIdx.x;
    const int jt   = cta >> 1;      // j-tile (16 h-units)
    const int bs   = cta & 1;       // batch half (32)
    const int nsub = warp & 1;      // 16-batch sub-half
    const int ksub = warp >> 1;     // K quarter

    // ---- prep: x -> single-fp16 fragment words (R14-verified) ----
    {
        const int XW = T_ * KT0 * B_ * 8;
        for (int w = cta * NT + tid; w < XW; w += NCTA * NT) {
            int sel = w & 1, qq = (w >> 1) & 3, b = (w >> 3) & 63;
            int kg = (w >> 9) & 15, t = w >> 13;
            int k0 = kg * 16 + qq * 2 + sel * 8;
            g_xx[w] = pk(x[((size_t)b * T_ + t) * DIN + k0],
                         x[((size_t)b * T_ + t) * DIN + k0 + 1]);
        }
    }
    // ---- zero initial state (buffer 1 read first) ----
    for (int i = cta * NT + tid; i < KTH * B_ * 8; i += NCTA * NT) {
        g_h0x[1][i] = 0u; g_h1x[1][i] = 0u;
    }
    for (int i = cta * NT + tid; i < B_ * H_; i += NCTA * NT) {
        g_h0f[1][i] = 0.f; g_h1f[1][i] = 0.f;
    }
    // ---- weights -> fp16 hi/lo fragment table (R5 layout) ----
    {
        const float* Wp[4] = { Wi0, Wh0, Wi1, Wh1 };
        const int    Kp[4] = { DIN, H_, H_, H_ };
        const size_t Fp[4] = { FB0, FB1, FB2, FB3 };
        for (int p = 0; p < 4; ++p) {
            const int K = Kp[p], KT = K / 16;
            const float* W = Wp[p];
            const int total = 64 * 3 * KT * 32;
            for (int i = cta * NT + tid; i < total; i += NCTA * NT) {
                int l = i & 31, item = i >> 5;
                int kg = item % KT, g = (item / KT) % 3, jtt = item / (KT * 3);
                int m = l >> 2, kb = 2 * (l & 3);
                const float* r0 = W + (size_t)(g * H_ + jtt * 16 + m) * K + kg * 16 + kb;
                const float* r1 = r0 + 8 * (size_t)K;
                float w00 = r0[0], w01 = r0[1], w02 = r0[8], w03 = r0[9];
                float w10 = r1[0], w11 = r1[1], w12 = r1[8], w13 = r1[9];
                uint4 hv, lv;
                hv.x = pk(w00, w01); hv.y = pk(w10, w11);
                hv.z = pk(w02, w03); hv.w = pk(w12, w13);
                lv.x = pk(resid(w00), resid(w01)); lv.y = pk(resid(w10), resid(w11));
                lv.z = pk(resid(w02), resid(w03)); lv.w = pk(resid(w12), resid(w13));
                size_t base = Fp[p] + ((size_t)(jtt * 3 + g) * KT + kg) * 64;
                g_wA[base + l] = hv;
                g_wA[base + 32 + l] = lv;
            }
        }
    }
    // ---- biases: thread gates (jl2, jl2+1) x batch tb ----
    const int jl2 = (tid >> 5) * 2, tb = tid & 31;
    const int gb  = bs * 32 + tb;
    float bv0[2][4], bv1[2][4];
#pragma unroll
    for (int jj = 0; jj < 2; ++jj) {
        int j = jt * 16 + jl2 + jj;
        bv0[jj][0] = bi0[j] + bh0[j];
        bv0[jj][1] = bi0[H_ + j] + bh0[H_ + j];
        bv0[jj][2] = bi0[2 * H_ + j];
        bv0[jj][3] = bh0[2 * H_ + j];
        bv1[jj][0] = bi1[j] + bh1[j];
        bv1[jj][1] = bi1[H_ + j] + bh1[H_ + j];
        bv1[jj][2] = bi1[2 * H_ + j];
        bv1[jj][3] = bh1[2 * H_ + j];
    }

    // ---- warp fragment pointers (4 chains per GEMM segment) ----
    const int kgs0 = ksub * 4;     // x segment: 4 kg per warp
    const int kgsH = ksub * 16;    // h segments: 16 kg per warp
    const uint4* b0 = g_wA + FB0 + (size_t)jt * 3 * KT0 * 64 + lane;
    const uint4* b1 = g_wA + FB1 + (size_t)jt * 3 * KTH * 64 + lane;
    const uint4* b2 = g_wA + FB2 + (size_t)jt * 3 * KTH * 64 + lane;
    const uint4* b3 = g_wA + FB3 + (size_t)jt * 3 * KTH * 64 + lane;
    const uint4* f0R = b0 + kgs0 * 64,               *f0Z = b0 + (KT0 + kgs0) * 64;
    const uint4* f0N = b0 + (2 * KT0 + kgs0) * 64,   *f0L = f0N + 32;
    const uint4* f1R = b1 + kgsH * 64,               *f1Z = b1 + (KTH + kgsH) * 64;
    const uint4* f1N = b1 + (2 * KTH + kgsH) * 64,   *f1L = f1N + 32;
    const uint4* f2R = b2 + kgsH * 64,               *f2Z = b2 + (KTH + kgsH) * 64;
    const uint4* f2N = b2 + (2 * KTH + kgsH) * 64,   *f2L = f2N + 32;
    const uint4* f3R = b3 + kgsH * 64,               *f3Z = b3 + (KTH + kgsH) * 64;
    const uint4* f3N = b3 + (2 * KTH + kgsH) * 64,   *f3L = f3N + 32;
    // B fragment lane offset (uint2 units): b = bs*32 + nsub*16 + (lane>>2)
    const unsigned boff = (unsigned)((bs * 32 + nsub * 16 + (lane >> 2)) * 4
                                     + (lane & 3));

    // publish helper lambda: write acc set into part[ksub][q]
    auto pub = [&](int q, float (&a)[2][4]) {
#pragma unroll
        for (int p = 0; p < 2; ++p)
#pragma unroll
            for (int e = 0; e < 4; ++e) {
                int jl = (lane >> 2) + 8 * (e >> 1);
                int bl = nsub * 16 + p * 8 + 2 * (lane & 3) + (e & 1);
                part[ksub][q][jl][bl] = a[p][e];
            }
    };
    auto pub2 = [&](int q, float (&a)[2][4], float (&b)[2][4]) {
#pragma unroll
        for (int p = 0; p < 2; ++p)
#pragma unroll
            for (int e = 0; e < 4; ++e) {
                int jl = (lane >> 2) + 8 * (e >> 1);
                int bl = nsub * 16 + p * 8 + 2 * (lane & 3) + (e & 1);
                part[ksub][q][jl][bl] = a[p][e] + b[p][e];
            }
    };

    unsigned gen = 0;
    grid_sync(++gen);   // prep visible

    for (int p = 0; p <= T_; ++p) {
        const int rb0 = (p + 1) & 1;
        // ======== layer 0 (t = p) ========
        if (p < T_) {
            float aR[2][4] = {}, aZ[2][4] = {}, aNm[2][4] = {}, aNx[2][4] = {};
            // x segment -> Ni
            mloop4<4>(f0R, f0Z, f0N, f0L,
                      (const uint2*)g_xx + (size_t)p * 4096 + kgs0 * 256 + boff,
                      aR, aZ, aNm, aNx);
            pub2(2, aNm, aNx);
#pragma unroll
            for (int pp = 0; pp < 2; ++pp)
#pragma unroll
                for (int e = 0; e < 4; ++e) { aNm[pp][e] = 0.f; aNx[pp][e] = 0.f; }
            // h segment -> Nh (R/Z continue)
            mloop4<16>(f1R, f1Z, f1N, f1L,
                       (const uint2*)g_h0x[rb0] + kgsH * 256 + boff,
                       aR, aZ, aNm, aNx);
            pub(0, aR); pub(1, aZ); pub2(3, aNm, aNx);
        }
        __syncthreads();
        if (p < T_) {   // gate layer0: h0(p)
#pragma unroll
            for (int jj = 0; jj < 2; ++jj) {
                int jl = jl2 + jj, j = jt * 16 + jl;
                float R = part[0][0][jl][tb] + part[1][0][jl][tb]
                        + part[2][0][jl][tb] + part[3][0][jl][tb];
                float Z = part[0][1][jl][tb] + part[1][1][jl][tb]
                        + part[2][1][jl][tb] + part[3][1][jl][tb];
                float Ni = part[0][2][jl][tb] + part[1][2][jl][tb]
                         + part[2][2][jl][tb] + part[3][2][jl][tb];
                float Nh = part[0][3][jl][tb] + part[1][3][jl][tb]
                         + part[2][3][jl][tb] + part[3][3][jl][tb];
                float r = sigf(R + bv0[jj][0]);
                float z = sigf(Z + bv0[jj][1]);
                float n = tanh_(Ni + bv0[jj][2] + r * (Nh + bv0[jj][3]));
                float hp = g_h0f[rb0][gb * H_ + j];
                float h  = n + z * (hp - n);
                g_h0f[p & 1][gb * H_ + j] = h;
                int kg = j >> 4, pw = (j & 15) >> 1, qq = pw & 3, sl = pw >> 2;
                unsigned idx = (unsigned)(((kg * 64 + gb) * 4 + qq) * 2 + sl);
                reinterpret_cast<unsigned short*>(g_h0x[p & 1] + idx)[j & 1] = hfb(h);
            }
        }
        __syncthreads();
        // ======== layer 1 (t = p-1) ========
        if (p > 0) {
            float aR[2][4] = {}, aZ[2][4] = {}, aNm[2][4] = {}, aNx[2][4] = {};
            // input segment (h0(p-1)) -> Ni
            mloop4<16>(f2R, f2Z, f2N, f2L,
                       (const uint2*)g_h0x[rb0] + kgsH * 256 + boff,
                       aR, aZ, aNm, aNx);
            pub2(2, aNm, aNx);
#pragma unroll
            for (int pp = 0; pp < 2; ++pp)
#pragma unroll
                for (int e = 0; e < 4; ++e) { aNm[pp][e] = 0.f; aNx[pp][e] = 0.f; }
            // hidden segment (h1(p-2)) -> Nh
            mloop4<16>(f3R, f3Z, f3N, f3L,
                       (const uint2*)g_h1x[p & 1] + kgsH * 256 + boff,
                       aR, aZ, aNm, aNx);
            pub(0, aR); pub(1, aZ); pub2(3, aNm, aNx);
        }
        __syncthreads();
        if (p > 0) {    // gate layer1: h1(p-1)
#pragma unroll
            for (int jj = 0; jj < 2; ++jj) {
                int jl = jl2 + jj, j = jt * 16 + jl;
                float R = part[0][0][jl][tb] + part[1][0][jl][tb]
                        + part[2][0][jl][tb] + part[3][0][jl][tb];
                float Z = part[0][1][jl][tb] + part[1][1][jl][tb]
                        + part[2][1][jl][tb] + part[3][1][jl][tb];
                float Ni = part[0][2][jl][tb] + part[1][2][jl][tb]
                         + part[2][2][jl][tb] + part[3][2][jl][tb];
                float Nh = part[0][3][jl][tb] + part[1][3][jl][tb]
                         + part[2][3][jl][tb] + part[3][3][jl][tb];
                float r = sigf(R + bv1[jj][0]);
                float z = sigf(Z + bv1[jj][1]);
                float n = tanh_(Ni + bv1[jj][2] + r * (Nh + bv1[jj][3]));
                float hp = g_h1f[p & 1][gb * H_ + j];
                float h  = n + z * (hp - n);
                g_h1f[(p + 1) & 1][gb * H_ + j] = h;
                int kg = j >> 4, pw = (j & 15) >> 1, qq = pw & 3, sl = pw >> 2;
                unsigned idx = (unsigned)(((kg * 64 + gb) * 4 + qq) * 2 + sl);
                reinterpret_cast<unsigned short*>(g_h1x[(p + 1) & 1] + idx)[j & 1] = hfb(h);
            }
        }
        grid_sync(++gen);
    }

    // ---- output projection: h1(511) in g_h1f[1] ----
    if (tid < 128) {
        const int o = cta * 2 + (tid >> 6);
        const int b = tid & 63;
        const float* w  = Wo + (size_t)o * H_;
        const float* hv = g_h1f[1] + (size_t)b * H_;
        float acc = 0.f;
#pragma unroll 4
        for (int k = 0; k < H_; k += 4) {
            float4 wv = *(const float4*)(w + k);
            float4 h4 = *(const float4*)(hv + k);
            acc += wv.x * h4.x + wv.y * h4.y + wv.z * h4.z + wv.w * h4.w;
        }
        out[(size_t)b * DOUT + o] = acc + bo[o];
    }

    // ---- reset persistent counters for next replay ----
    __syncthreads();
    if (tid == 0) {
        unsigned old = atomicAdd(&g_done, 1u);
        if (old == NCTA - 1u) {
            g_bar = 0u;
            g_done = 0u;
            __threadfence();
        }
    }
}

extern "C" void kernel_launch(void* const* d_in, const int* in_sizes, int n_in,
                              void* d_out, int out_size)
{
    gru_loc<<<NCTA, NT>>>(
        (const float*)d_in[0], (const float*)d_in[1], (const float*)d_in[2],
        (const float*)d_in[3], (const float*)d_in[4], (const float*)d_in[5],
        (const float*)d_in[6], (const float*)d_in[7], (const float*)d_in[8],
        (const float*)d_in[9], (const float*)d_in[10], (float*)d_out);
}

// round 17
// speedup vs baseline: 1.3767x; 1.0085x over previous
#include <cuda_runtime.h>
#include <cuda_fp16.h>

#define B_   64
#define T_   512
#define DIN  256
#define H_   1024
#define DOUT 256
#define NCTA 128
#define NT   256

constexpr int KT0 = 16;
constexpr int KTH = 64;
constexpr size_t FSZ0 = (size_t)64 * 3 * KT0 * 64;
constexpr size_t FSZH = (size_t)64 * 3 * KTH * 64;
constexpr size_t FB0 = 0, FB1 = FSZ0, FB2 = FSZ0 + FSZH, FB3 = FSZ0 + 2 * FSZH;
constexpr int DYNSM = 4 * 7 * 16 * 33 * 4;   // 59136 B part buffer

__device__ uint4 g_wA[FSZ0 + 3 * FSZH];            // fp16 frag table (hi, lo)
__device__ float g_h0f[2][B_ * H_], g_h1f[2][B_ * H_];
__device__ unsigned g_h0x[2][KTH * B_ * 8];        // fp16 act frags [kg][b][qq][sel]
__device__ unsigned g_h1x[2][KTH * B_ * 8];
__device__ unsigned g_xx[(size_t)T_ * KT0 * B_ * 8];
__device__ float g_gx[(size_t)T_ * 3 * H_ * B_];   // Wi0*x partials [t][q][j][b]
__device__ unsigned g_bar, g_done;

__device__ __forceinline__ unsigned short hfb(float v) {
    __half h = __float2half_rn(v);
    return *reinterpret_cast<unsigned short*>(&h);
}
__device__ __forceinline__ float h2f(unsigned short u) {
    __half h = *reinterpret_cast<__half*>(&u);
    return __half2float(h);
}
__device__ __forceinline__ unsigned pk(float a, float b) {
    return (unsigned)hfb(a) | ((unsigned)hfb(b) << 16);
}
__device__ __forceinline__ float resid(float w) { return w - h2f(hfb(w)); }
__device__ __forceinline__ float sigf(float x) {
    return __fdividef(1.0f, 1.0f + __expf(-x));
}
__device__ __forceinline__ float tanh_(float x) {
    return __fdividef(2.0f, 1.0f + __expf(-2.0f * x)) - 1.0f;
}
__device__ __forceinline__ void mmaf16(float (&d)[4], const uint4 a,
                                       unsigned b0, unsigned b1) {
    asm volatile(
        "mma.sync.aligned.m16n8k16.row.col.f32.f16.f16.f32 "
        "{%0,%1,%2,%3},{%4,%5,%6,%7},{%8,%9},{%0,%1,%2,%3};"
        : "+f"(d[0]), "+f"(d[1]), "+f"(d[2]), "+f"(d[3])
        : "r"(a.x), "r"(a.y), "r"(a.z), "r"(a.w), "r"(b0), "r"(b1));
}
__device__ __forceinline__ void grid_sync(unsigned gen) {
    __syncthreads();
    if (threadIdx.x == 0) {
        __threadfence();
        atomicAdd(&g_bar, 1u);
        while (*((volatile unsigned*)&g_bar) < gen * NCTA) { }
        __threadfence();
    }
    __syncthreads();
}

// 8 independent MMAs per kg: 4 A-chains (R,Z,Nhi,Nlo) x 2 n8-tiles.
template<int CNT>
__device__ __forceinline__ void mloop4(
    const uint4* __restrict__ fR, const uint4* __restrict__ fZ,
    const uint4* __restrict__ fNh, const uint4* __restrict__ fNl,
    const uint2* __restrict__ bp,
    float (&aR)[2][4], float (&aZ)[2][4],
    float (&aNm)[2][4], float (&aNx)[2][4])
{
#pragma unroll 4
    for (int k = 0; k < CNT; ++k) {
        uint4 A0 = fR[0], A1 = fZ[0], A2 = fNh[0], A3 = fNl[0];
        uint2 v0 = bp[0], v1 = bp[32];
        mmaf16(aR[0], A0, v0.x, v0.y);  mmaf16(aR[1], A0, v1.x, v1.y);
        mmaf16(aZ[0], A1, v0.x, v0.y);  mmaf16(aZ[1], A1, v1.x, v1.y);
        mmaf16(aNm[0], A2, v0.x, v0.y); mmaf16(aNm[1], A2, v1.x, v1.y);
        mmaf16(aNx[0], A3, v0.x, v0.y); mmaf16(aNx[1], A3, v1.x, v1.y);
        fR += 64; fZ += 64; fNh += 64; fNl += 64; bp += 256;
    }
}

#define PART(ks, sl, jl, bl) part[((((ks) * 7 + (sl)) * 16 + (jl)) * 33) + (bl)]

__global__ void __launch_bounds__(NT, 1) gru_pc(
    const float* __restrict__ x,
    const float* __restrict__ Wi0, const float* __restrict__ Wh0,
    const float* __restrict__ bi0, const float* __restrict__ bh0,
    const float* __restrict__ Wi1, const float* __restrict__ Wh1,
    const float* __restrict__ bi1, const float* __restrict__ bh1,
    const float* __restrict__ Wo,  const float* __restrict__ bo,
    float* __restrict__ out)
{
    extern __shared__ float part[];   // [4 ksub][7 slots][16 jl][33 bl]

    const int tid  = threadIdx.x, lane = tid & 31, warp = tid >> 5;
    const int cta  = blockIdx.x;
    const int jt   = cta >> 1;      // j-tile (16 h-units)
    const int bs   = cta & 1;       // batch half (32)
    const int nsub = warp & 1;      // 16-batch sub-half
    const int ksub = warp >> 1;     // K quarter

    // ---- prep: x -> single-fp16 fragment words ----
    {
        const int XW = T_ * KT0 * B_ * 8;
        for (int w = cta * NT + tid; w < XW; w += NCTA * NT) {
            int sel = w & 1, qq = (w >> 1) & 3, b = (w >> 3) & 63;
            int kg = (w >> 9) & 15, t = w >> 13;
            int k0 = kg * 16 + qq * 2 + sel * 8;
            g_xx[w] = pk(x[((size_t)b * T_ + t) * DIN + k0],
                         x[((size_t)b * T_ + t) * DIN + k0 + 1]);
        }
    }
    // ---- zero initial state (buffer 1 read first) ----
    for (int i = cta * NT + tid; i < KTH * B_ * 8; i += NCTA * NT) {
        g_h0x[1][i] = 0u; g_h1x[1][i] = 0u;
    }
    for (int i = cta * NT + tid; i < B_ * H_; i += NCTA * NT) {
        g_h0f[1][i] = 0.f; g_h1f[1][i] = 0.f;
    }
    // ---- weights -> fp16 hi/lo fragment table (R5 layout) ----
    {
        const float* Wp[4] = { Wi0, Wh0, Wi1, Wh1 };
        const int    Kp[4] = { DIN, H_, H_, H_ };
        const size_t Fp[4] = { FB0, FB1, FB2, FB3 };
        for (int p = 0; p < 4; ++p) {
            const int K = Kp[p], KT = K / 16;
            const float* W = Wp[p];
            const int total = 64 * 3 * KT * 32;
            for (int i = cta * NT + tid; i < total; i += NCTA * NT) {
                int l = i & 31, item = i >> 5;
                int kg = item % KT, g = (item / KT) % 3, jtt = item / (KT * 3);
                int m = l >> 2, kb = 2 * (l & 3);
                const float* r0 = W + (size_t)(g * H_ + jtt * 16 + m) * K + kg * 16 + kb;
                const float* r1 = r0 + 8 * (size_t)K;
                float w00 = r0[0], w01 = r0[1], w02 = r0[8], w03 = r0[9];
                float w10 = r1[0], w11 = r1[1], w12 = r1[8], w13 = r1[9];
                uint4 hv, lv;
                hv.x = pk(w00, w01); hv.y = pk(w10, w11);
                hv.z = pk(w02, w03); hv.w = pk(w12, w13);
                lv.x = pk(resid(w00), resid(w01)); lv.y = pk(resid(w10), resid(w11));
                lv.z = pk(resid(w02), resid(w03)); lv.w = pk(resid(w12), resid(w13));
                size_t base = Fp[p] + ((size_t)(jtt * 3 + g) * KT + kg) * 64;
                g_wA[base + l] = hv;
                g_wA[base + 32 + l] = lv;
            }
        }
    }
    // ---- biases ----
    const int jl2 = (tid >> 5) * 2, tb = tid & 31;
    const int gb  = bs * 32 + tb;
    float bv0[2][4], bv1[2][4];
#pragma unroll
    for (int jj = 0; jj < 2; ++jj) {
        int j = jt * 16 + jl2 + jj;
        bv0[jj][0] = bi0[j] + bh0[j];
        bv0[jj][1] = bi0[H_ + j] + bh0[H_ + j];
        bv0[jj][2] = bi0[2 * H_ + j];
        bv0[jj][3] = bh0[2 * H_ + j];
        bv1[jj][0] = bi1[j] + bh1[j];
        bv1[jj][1] = bi1[H_ + j] + bh1[H_ + j];
        bv1[jj][2] = bi1[2 * H_ + j];
        bv1[jj][3] = bh1[2 * H_ + j];
    }

    // ---- fragment pointers ----
    const int kgsH = ksub * 16;
    const uint4* b1 = g_wA + FB1 + (size_t)jt * 3 * KTH * 64 + lane;
    const uint4* b2 = g_wA + FB2 + (size_t)jt * 3 * KTH * 64 + lane;
    const uint4* b3 = g_wA + FB3 + (size_t)jt * 3 * KTH * 64 + lane;
    const uint4* f1R = b1 + kgsH * 64,             *f1Z = b1 + (KTH + kgsH) * 64;
    const uint4* f1N = b1 + (2 * KTH + kgsH) * 64, *f1L = f1N + 32;
    const uint4* f2R = b2 + kgsH * 64,             *f2Z = b2 + (KTH + kgsH) * 64;
    const uint4* f2N = b2 + (2 * KTH + kgsH) * 64, *f2L = f2N + 32;
    const uint4* f3R = b3 + kgsH * 64,             *f3Z = b3 + (KTH + kgsH) * 64;
    const uint4* f3N = b3 + (2 * KTH + kgsH) * 64, *f3L = f3N + 32;
    const unsigned boff = (unsigned)((bs * 32 + nsub * 16 + (lane >> 2)) * 4
                                     + (lane & 3));

    auto pub = [&](int sl, float (&a)[2][4]) {
#pragma unroll
        for (int p = 0; p < 2; ++p)
#pragma unroll
            for (int e = 0; e < 4; ++e) {
                int jl = (lane >> 2) + 8 * (e >> 1);
                int bl = nsub * 16 + p * 8 + 2 * (lane & 3) + (e & 1);
                PART(ksub, sl, jl, bl) = a[p][e];
            }
    };
    auto pub2 = [&](int sl, float (&a)[2][4], float (&b)[2][4]) {
#pragma unroll
        for (int p = 0; p < 2; ++p)
#pragma unroll
            for (int e = 0; e < 4; ++e) {
                int jl = (lane >> 2) + 8 * (e >> 1);
                int bl = nsub * 16 + p * 8 + 2 * (lane & 3) + (e & 1);
                PART(ksub, sl, jl, bl) = a[p][e] + b[p][e];
            }
    };

    unsigned gen = 0;
    grid_sync(++gen);   // prep visible (g_wA, g_xx, zeros)

    // ---- precompute gi0 = Wi0*x(t) for ALL t (time-parallel, CTA-local) ----
    {
        const uint4* pR = g_wA + FB0 + (size_t)jt * 3 * KT0 * 64 + lane;
        const uint4* pZ = pR + KT0 * 64;
        const uint4* pN = pR + 2 * KT0 * 64;
        const uint4* pL = pN + 32;
        for (int t = warp; t < T_; t += 8) {
            float aR[4][4] = {}, aZ[4][4] = {}, aNm[4][4] = {}, aNx[4][4] = {};
            const uint2* xb = (const uint2*)g_xx + (size_t)t * 4096
                              + ((bs * 32 + (lane >> 2)) * 4 + (lane & 3));
#pragma unroll 4
            for (int kg = 0; kg < KT0; ++kg) {
                uint4 A0 = pR[kg * 64], A1 = pZ[kg * 64];
                uint4 A2 = pN[kg * 64], A3 = pL[kg * 64];
                uint2 v[4];
#pragma unroll
                for (int q = 0; q < 4; ++q) v[q] = xb[kg * 256 + q * 32];
#pragma unroll
                for (int q = 0; q < 4; ++q) {
                    mmaf16(aR[q],  A0, v[q].x, v[q].y);
                    mmaf16(aZ[q],  A1, v[q].x, v[q].y);
                    mmaf16(aNm[q], A2, v[q].x, v[q].y);
                    mmaf16(aNx[q], A3, v[q].x, v[q].y);
                }
            }
            size_t o = (size_t)t * 3 * H_ * B_;
#pragma unroll
            for (int q = 0; q < 4; ++q)
#pragma unroll
                for (int e = 0; e < 4; ++e) {
                    int j = jt * 16 + (lane >> 2) + 8 * (e >> 1);
                    int b = bs * 32 + q * 8 + 2 * (lane & 3) + (e & 1);
                    g_gx[o + (size_t)j * 64 + b] = aR[q][e];
                    g_gx[o + (size_t)(H_ + j) * 64 + b] = aZ[q][e];
                    g_gx[o + (size_t)(2 * H_ + j) * 64 + b] = aNm[q][e] + aNx[q][e];
                }
        }
    }
    // gi0 is produced and consumed by the SAME CTA -> no barrier needed.

    for (int p = 0; p <= T_; ++p) {
        const int rb0 = (p + 1) & 1;
        // prefetch gi0 contributions (DRAM latency hidden behind MMAs)
        float gx[2][3];
        if (p < T_) {
#pragma unroll
            for (int jj = 0; jj < 2; ++jj) {
                size_t o = (size_t)p * 3 * H_ * B_
                           + (size_t)(jt * 16 + jl2 + jj) * 64 + gb;
                gx[jj][0] = g_gx[o];
                gx[jj][1] = g_gx[o + (size_t)H_ * 64];
                gx[jj][2] = g_gx[o + (size_t)2 * H_ * 64];
            }
        }
        // ---- layer0 h-segment (Wh0 x h0(p-1)) ----
        if (p < T_) {
            float aR[2][4] = {}, aZ[2][4] = {}, aNm[2][4] = {}, aNx[2][4] = {};
            mloop4<16>(f1R, f1Z, f1N, f1L,
                       (const uint2*)g_h0x[rb0] + kgsH * 256 + boff,
                       aR, aZ, aNm, aNx);
            pub(0, aR); pub(1, aZ); pub2(2, aNm, aNx);
        }
        // ---- layer1 (t = p-1): Wi1 x h0(p-1), Wh1 x h1(p-2) ----
        if (p > 0) {
            float aR[2][4] = {}, aZ[2][4] = {}, aNm[2][4] = {}, aNx[2][4] = {};
            mloop4<16>(f2R, f2Z, f2N, f2L,
                       (const uint2*)g_h0x[rb0] + kgsH * 256 + boff,
                       aR, aZ, aNm, aNx);
            pub2(5, aNm, aNx);
#pragma unroll
            for (int pp = 0; pp < 2; ++pp)
#pragma unroll
                for (int e = 0; e < 4; ++e) { aNm[pp][e] = 0.f; aNx[pp][e] = 0.f; }
            mloop4<16>(f3R, f3Z, f3N, f3L,
                       (const uint2*)g_h1x[p & 1] + kgsH * 256 + boff,
                       aR, aZ, aNm, aNx);
            pub(3, aR); pub(4, aZ); pub2(6, aNm, aNx);
        }
        __syncthreads();
        // ---- gate layer0: h0(p) ----
        if (p < T_) {
#pragma unroll
            for (int jj = 0; jj < 2; ++jj) {
                int jl = jl2 + jj, j = jt * 16 + jl;
                float R  = PART(0,0,jl,tb) + PART(1,0,jl,tb)
                         + PART(2,0,jl,tb) + PART(3,0,jl,tb);
                float Z  = PART(0,1,jl,tb) + PART(1,1,jl,tb)
                         + PART(2,1,jl,tb) + PART(3,1,jl,tb);
                float Nh = PART(0,2,jl,tb) + PART(1,2,jl,tb)
                         + PART(2,2,jl,tb) + PART(3,2,jl,tb);
                float r = sigf(R + gx[jj][0] + bv0[jj][0]);
                float z = sigf(Z + gx[jj][1] + bv0[jj][1]);
                float n = tanh_(gx[jj][2] + bv0[jj][2] + r * (Nh + bv0[jj][3]));
                float hp = g_h0f[rb0][gb * H_ + j];
                float h  = n + z * (hp - n);
                g_h0f[p & 1][gb * H_ + j] = h;
                int kg = j >> 4, pw = (j & 15) >> 1, qq = pw & 3, sl = pw >> 2;
                unsigned idx = (unsigned)(((kg * 64 + gb) * 4 + qq) * 2 + sl);
                reinterpret_cast<unsigned short*>(g_h0x[p & 1] + idx)[j & 1] = hfb(h);
            }
        }
        // ---- gate layer1: h1(p-1) ----
        if (p > 0) {
#pragma unroll
            for (int jj = 0; jj < 2; ++jj) {
                int jl = jl2 + jj, j = jt * 16 + jl;
                float R  = PART(0,3,jl,tb) + PART(1,3,jl,tb)
                         + PART(2,3,jl,tb) + PART(3,3,jl,tb);
                float Z  = PART(0,4,jl,tb) + PART(1,4,jl,tb)
                         + PART(2,4,jl,tb) + PART(3,4,jl,tb);
                float Ni = PART(0,5,jl,tb) + PART(1,5,jl,tb)
                         + PART(2,5,jl,tb) + PART(3,5,jl,tb);
                float Nh = PART(0,6,jl,tb) + PART(1,6,jl,tb)
                         + PART(2,6,jl,tb) + PART(3,6,jl,tb);
                float r = sigf(R + bv1[jj][0]);
                float z = sigf(Z + bv1[jj][1]);
                float n = tanh_(Ni + bv1[jj][2] + r * (Nh + bv1[jj][3]));
                float hp = g_h1f[p & 1][gb * H_ + j];
                float h  = n + z * (hp - n);
                g_h1f[(p + 1) & 1][gb * H_ + j] = h;
                int kg = j >> 4, pw = (j & 15) >> 1, qq = pw & 3, sl = pw >> 2;
                unsigned idx = (unsigned)(((kg * 64 + gb) * 4 + qq) * 2 + sl);
                reinterpret_cast<unsigned short*>(g_h1x[(p + 1) & 1] + idx)[j & 1] = hfb(h);
            }
        }
        grid_sync(++gen);
    }

    // ---- output projection: h1(511) in g_h1f[1] ----
    if (tid < 128) {
        const int o = cta * 2 + (tid >> 6);
        const int b = tid & 63;
        const float* w  = Wo + (size_t)o * H_;
        const float* hv = g_h1f[1] + (size_t)b * H_;
        float acc = 0.f;
#pragma unroll 4
        for (int k = 0; k < H_; k += 4) {
            float4 wv = *(const float4*)(w + k);
            float4 h4 = *(const float4*)(hv + k);
            acc += wv.x * h4.x + wv.y * h4.y + wv.z * h4.z + wv.w * h4.w;
        }
        out[(size_t)b * DOUT + o] = acc + bo[o];
    }

    // ---- reset persistent counters for next replay ----
    __syncthreads();
    if (tid == 0) {
        unsigned old = atomicAdd(&g_done, 1u);
        if (old == NCTA - 1u) {
            g_bar = 0u;
            g_done = 0u;
            __threadfence();
        }
    }
}

extern "C" void kernel_launch(void* const* d_in, const int* in_sizes, int n_in,
                              void* d_out, int out_size)
{
    cudaFuncSetAttribute(gru_pc, cudaFuncAttributeMaxDynamicSharedMemorySize,
                         DYNSM);
    gru_pc<<<NCTA, NT, DYNSM>>>(
        (const float*)d_in[0], (const float*)d_in[1], (const float*)d_in[2],
        (const float*)d_in[3], (const float*)d_in[4], (const float*)d_in[5],
        (const float*)d_in[6], (const float*)d_in[7], (const float*)d_in[8],
        (const float*)d_in[9], (const float*)d_in[10], (float*)d_out);
}